// round 9
// baseline (speedup 1.0000x reference)
#include <cuda_runtime.h>
#include <math.h>
#include <stdint.h>

// ---------------- problem constants ----------------
#define BATCH 64
#define HS_   56
#define CC    128
#define NH_   4
#define HID_  512
#define PIX   (BATCH*HS_*HS_)      // 200704
#define M1_   PIX                  // window-token rows
#define M2_   (BATCH*28*28)        // 50176 merged rows

// weight scratch offsets (floats)
#define WOFF_QKV   0
#define WOFF_PROJ  49152
#define WOFF_FC1   65536
#define WOFF_FC2   131072
#define WOFF_MRG   196608
#define WTOT       327680

// ---------------- scratch (static device memory; allocation-free) ----------
__device__ float g_hw[(size_t)M1_*CC];       // LN output (tf32-rounded bits)
__device__ float g_qkv[(size_t)M1_*3*CC];    // qkv projections (tf32-rounded)
__device__ float g_o[(size_t)M1_*CC];        // attn out / merged xm (tf32-rounded)
__device__ float g_xres[(size_t)M1_*CC];     // residual stream (fp32, pixel layout)
__device__ float g_fc1[(size_t)M1_*HID_];    // fc1+gelu output (tf32-rounded)
__device__ float g_wt[WTOT];                 // tf32-rounded weights
__device__ float g_bias[64*4*2401];          // combined rpb+mask per (wimg, head)

// ---------------- helpers ----------------
__device__ __forceinline__ uint32_t f2tf32(float x) {
    uint32_t r; asm("cvt.rna.tf32.f32 %0, %1;" : "=r"(r) : "f"(x)); return r;
}
__device__ __forceinline__ float tf32r(float x) { return __uint_as_float(f2tf32(x)); }
__device__ __forceinline__ void mma_tf32(float* c, const uint32_t* a, uint32_t b0, uint32_t b1) {
    asm volatile("mma.sync.aligned.m16n8k8.row.col.f32.tf32.tf32.f32 "
        "{%0,%1,%2,%3}, {%4,%5,%6,%7}, {%8,%9}, {%0,%1,%2,%3};\n"
        : "+f"(c[0]), "+f"(c[1]), "+f"(c[2]), "+f"(c[3])
        : "r"(a[0]), "r"(a[1]), "r"(a[2]), "r"(a[3]), "r"(b0), "r"(b1));
}
__device__ __forceinline__ void cp_async16(uint32_t saddr, const void* gptr) {
    asm volatile("cp.async.cg.shared.global [%0], [%1], 16;\n" :: "r"(saddr), "l"(gptr));
}
__device__ __forceinline__ void cp_commit() { asm volatile("cp.async.commit_group;\n"); }
__device__ __forceinline__ void cp_wait1() { asm volatile("cp.async.wait_group 1;\n"); }
__device__ __forceinline__ void cp_wait0() { asm volatile("cp.async.wait_group 0;\n"); }

// ---------------- weight pre-round ----------------
__global__ void round_w_kernel(const float* __restrict__ qkv_w, const float* __restrict__ proj_w,
                               const float* __restrict__ fc1_w, const float* __restrict__ fc2_w,
                               const float* __restrict__ merge_w)
{
    int i = blockIdx.x * blockDim.x + threadIdx.x;
    float v;
    if      (i < WOFF_PROJ) v = qkv_w[i];
    else if (i < WOFF_FC1)  v = proj_w[i - WOFF_PROJ];
    else if (i < WOFF_FC2)  v = fc1_w[i - WOFF_FC1];
    else if (i < WOFF_MRG)  v = fc2_w[i - WOFF_FC2];
    else                    v = merge_w[i - WOFF_MRG];
    g_wt[i] = tf32r(v);
}

// ---------------- combined attention bias table: rpb[rel]+mask ------------
__global__ void bias_prep_kernel(const float* __restrict__ rpb,
                                 const int* __restrict__ rel,
                                 const float* __restrict__ mask)
{
    int wimg = blockIdx.x, h = blockIdx.y;
    float* dst = g_bias + ((size_t)wimg*4 + h)*2401;
    const float* msk = mask + (size_t)wimg*2401;
    for (int i = threadIdx.x; i < 2401; i += blockDim.x)
        dst[i] = rpb[rel[i]*4 + h] + msk[i];
}

// ---------------- LN1 + roll(-3,-3) + window partition (tf32-rounded out) --
__global__ void ln1_win_kernel(const float* __restrict__ x,
                               const float* __restrict__ gw,
                               const float* __restrict__ gb)
{
    int warp = (blockIdx.x * blockDim.x + threadIdx.x) >> 5;
    int lane = threadIdx.x & 31;
    int b   = warp / 3136;
    int rem = warp - b * 3136;
    int i = rem / 56;
    int j = rem - i * 56;
    int si = i + 3; if (si >= 56) si -= 56;
    int sj = j + 3; if (sj >= 56) sj -= 56;
    float4 v = *(const float4*)(x + ((((size_t)b*56 + si)*56) + sj)*128 + lane*4);
    float s  = v.x + v.y + v.z + v.w;
    float ss = v.x*v.x + v.y*v.y + v.z*v.z + v.w*v.w;
    #pragma unroll
    for (int o = 16; o; o >>= 1) {
        s  += __shfl_xor_sync(0xffffffffu, s,  o);
        ss += __shfl_xor_sync(0xffffffffu, ss, o);
    }
    float mean = s * (1.0f/128.0f);
    float var  = ss * (1.0f/128.0f) - mean*mean;
    float rstd = rsqrtf(var + 1e-5f);
    float4 wv = *(const float4*)(gw + lane*4);
    float4 bv = *(const float4*)(gb + lane*4);
    float4 o4;
    o4.x = tf32r((v.x - mean)*rstd*wv.x + bv.x);
    o4.y = tf32r((v.y - mean)*rstd*wv.y + bv.y);
    o4.z = tf32r((v.z - mean)*rstd*wv.z + bv.z);
    o4.w = tf32r((v.w - mean)*rstd*wv.w + bv.w);
    int i7 = i / 7, j7 = j / 7;
    int widx = i7*8 + j7;
    int n    = (i - i7*7)*7 + (j - j7*7);
    size_t row = (size_t)(b*64 + widx)*49 + n;
    *(float4*)(g_hw + row*128 + lane*4) = o4;
}

// ---------------- LN2 (pixel layout): g_xres -> g_hw (tf32-rounded) -------
__global__ void ln2_kernel(const float* __restrict__ gw, const float* __restrict__ gb)
{
    int warp = (blockIdx.x * blockDim.x + threadIdx.x) >> 5;
    int lane = threadIdx.x & 31;
    float4 v = *(const float4*)(g_xres + (size_t)warp*128 + lane*4);
    float s  = v.x + v.y + v.z + v.w;
    float ss = v.x*v.x + v.y*v.y + v.z*v.z + v.w*v.w;
    #pragma unroll
    for (int o = 16; o; o >>= 1) {
        s  += __shfl_xor_sync(0xffffffffu, s,  o);
        ss += __shfl_xor_sync(0xffffffffu, ss, o);
    }
    float mean = s * (1.0f/128.0f);
    float var  = ss * (1.0f/128.0f) - mean*mean;
    float rstd = rsqrtf(var + 1e-5f);
    float4 wv = *(const float4*)(gw + lane*4);
    float4 bv = *(const float4*)(gb + lane*4);
    float4 o4;
    o4.x = tf32r((v.x - mean)*rstd*wv.x + bv.x);
    o4.y = tf32r((v.y - mean)*rstd*wv.y + bv.y);
    o4.z = tf32r((v.z - mean)*rstd*wv.z + bv.z);
    o4.w = tf32r((v.w - mean)*rstd*wv.w + bv.w);
    *(float4*)(g_hw + (size_t)warp*128 + lane*4) = o4;
}

// ---------------- patch-merge gather + LN(512): g_xres -> g_o (rounded) ---
__global__ void merge_ln_kernel(const float* __restrict__ gw, const float* __restrict__ gb)
{
    int warp = (blockIdx.x * blockDim.x + threadIdx.x) >> 5;
    int lane = threadIdx.x & 31;
    int b   = warp / 784;
    int rem = warp - b * 784;
    int i2 = rem / 28;
    int j2 = rem - i2 * 28;
    int i0 = 2*i2, j0 = 2*j2;
    const float* p0 = g_xres + (((size_t)b*56 + i0    )*56 + j0    )*128;
    const float* p1 = g_xres + (((size_t)b*56 + i0 + 1)*56 + j0    )*128;
    const float* p2 = g_xres + (((size_t)b*56 + i0    )*56 + j0 + 1)*128;
    const float* p3 = g_xres + (((size_t)b*56 + i0 + 1)*56 + j0 + 1)*128;
    float4 v[4];
    v[0] = *(const float4*)(p0 + lane*4);
    v[1] = *(const float4*)(p1 + lane*4);
    v[2] = *(const float4*)(p2 + lane*4);
    v[3] = *(const float4*)(p3 + lane*4);
    float s = 0.f, ss = 0.f;
    #pragma unroll
    for (int q = 0; q < 4; q++) {
        s  += v[q].x + v[q].y + v[q].z + v[q].w;
        ss += v[q].x*v[q].x + v[q].y*v[q].y + v[q].z*v[q].z + v[q].w*v[q].w;
    }
    #pragma unroll
    for (int o = 16; o; o >>= 1) {
        s  += __shfl_xor_sync(0xffffffffu, s,  o);
        ss += __shfl_xor_sync(0xffffffffu, ss, o);
    }
    float mean = s * (1.0f/512.0f);
    float var  = ss * (1.0f/512.0f) - mean*mean;
    float rstd = rsqrtf(var + 1e-5f);
    float* out = g_o + (size_t)warp*512;
    #pragma unroll
    for (int q = 0; q < 4; q++) {
        int c = q*128 + lane*4;
        float4 wv = *(const float4*)(gw + c);
        float4 bv = *(const float4*)(gb + c);
        float4 o4;
        o4.x = tf32r((v[q].x - mean)*rstd*wv.x + bv.x);
        o4.y = tf32r((v[q].y - mean)*rstd*wv.y + bv.y);
        o4.z = tf32r((v[q].z - mean)*rstd*wv.z + bv.z);
        o4.w = tf32r((v[q].w - mean)*rstd*wv.w + bv.w);
        *(float4*)(out + c) = o4;
    }
}

// ---------------- MMA attention: block = one window, warp = one head ------
#define AQ_STR 132
#define AK_STR 132
#define AV_STR 136
#define AP_STR 60
#define AOFF_K (64*AQ_STR)                  // 8448
#define AOFF_V (AOFF_K + 56*AK_STR)         // 15840
#define AOFF_P (AOFF_V + 56*AV_STR)         // 23456
#define AOFF_I (AOFF_P + 4*16*AP_STR)       // 27296
#define ATT_SMEM ((AOFF_I + 4*16)*4)        // 109440 bytes

__global__ __launch_bounds__(128) void attn_kernel(
    const float* __restrict__ qkv, float* __restrict__ outp)
{
    extern __shared__ float sm[];
    float* qs = sm;
    float* ks = sm + AOFF_K;
    float* vs = sm + AOFF_V;
    const int t    = threadIdx.x;
    const int warp = t >> 5;
    const int lane = t & 31;
    const int win  = blockIdx.x;
    float* Pt   = sm + AOFF_P + warp*16*AP_STR;
    float* invs = sm + AOFF_I + warp*16;

    const float* base = qkv + (size_t)win*49*384;
    for (int idx = t; idx < 49*96; idx += 128) {
        int row = idx / 96;
        int sub = idx - row*96;
        int kind = sub >> 5;
        int c4 = sub & 31;
        float4 v = *(const float4*)(base + (size_t)row*384 + kind*128 + c4*4);
        float* dst = (kind == 0 ? qs + row*AQ_STR :
                      kind == 1 ? ks + row*AK_STR : vs + row*AV_STR) + c4*4;
        *(float4*)dst = v;
    }
    for (int idx = t; idx < 7*AV_STR; idx += 128) {
        int r = idx / AV_STR, c = idx - r*AV_STR;
        vs[(49+r)*AV_STR + c] = 0.f;
        if (c < AK_STR) ks[(49+r)*AK_STR + c] = 0.f;
    }
    __syncthreads();

    const int h   = warp;
    const int qr  = lane >> 2;
    const int qc  = lane & 3;
    const int h32 = h * 32;
    const float* comb = g_bias + (size_t)((win & 63)*4 + h)*2401;
    float* obase = outp + (size_t)win*49*128 + h32;

    for (int mt = 0; mt < 4; mt++) {
        const int r0 = mt*16 + qr;
        const int r1 = r0 + 8;
        float s[7][4];
        #pragma unroll
        for (int jn = 0; jn < 7; jn++)
            #pragma unroll
            for (int c = 0; c < 4; c++) s[jn][c] = 0.f;
        #pragma unroll
        for (int kb = 0; kb < 32; kb += 8) {
            uint32_t a[4];
            a[0] = __float_as_uint(qs[(size_t)r0*AQ_STR + h32 + kb + qc    ]);
            a[1] = __float_as_uint(qs[(size_t)r1*AQ_STR + h32 + kb + qc    ]);
            a[2] = __float_as_uint(qs[(size_t)r0*AQ_STR + h32 + kb + qc + 4]);
            a[3] = __float_as_uint(qs[(size_t)r1*AQ_STR + h32 + kb + qc + 4]);
            #pragma unroll
            for (int jn = 0; jn < 7; jn++) {
                int n0 = jn*8 + qr;
                uint32_t b0 = __float_as_uint(ks[(size_t)n0*AK_STR + h32 + kb + qc    ]);
                uint32_t b1 = __float_as_uint(ks[(size_t)n0*AK_STR + h32 + kb + qc + 4]);
                mma_tf32(s[jn], a, b0, b1);
            }
        }
        const bool v0 = (r0 < 49), v1 = (r1 < 49);
        float mx0 = -1e30f, mx1 = -1e30f;
        #pragma unroll
        for (int jn = 0; jn < 7; jn++) {
            #pragma unroll
            for (int e = 0; e < 2; e++) {
                int col = jn*8 + qc*2 + e;
                if (col < 49) {
                    if (v0) s[jn][e]     += comb[r0*49 + col];
                    if (v1) s[jn][2 + e] += comb[r1*49 + col];
                } else {
                    s[jn][e] = -1e30f; s[jn][2 + e] = -1e30f;
                }
                mx0 = fmaxf(mx0, s[jn][e]);
                mx1 = fmaxf(mx1, s[jn][2 + e]);
            }
        }
        #pragma unroll
        for (int o = 1; o <= 2; o <<= 1) {
            mx0 = fmaxf(mx0, __shfl_xor_sync(0xffffffffu, mx0, o));
            mx1 = fmaxf(mx1, __shfl_xor_sync(0xffffffffu, mx1, o));
        }
        float sum0 = 0.f, sum1 = 0.f;
        #pragma unroll
        for (int jn = 0; jn < 7; jn++) {
            #pragma unroll
            for (int e = 0; e < 2; e++) {
                int col = jn*8 + qc*2 + e;
                float e0 = __expf(s[jn][e]     - mx0);
                float e1 = __expf(s[jn][2 + e] - mx1);
                sum0 += e0; sum1 += e1;
                Pt[qr*AP_STR       + col] = tf32r(e0);
                Pt[(qr + 8)*AP_STR + col] = tf32r(e1);
            }
        }
        #pragma unroll
        for (int o = 1; o <= 2; o <<= 1) {
            sum0 += __shfl_xor_sync(0xffffffffu, sum0, o);
            sum1 += __shfl_xor_sync(0xffffffffu, sum1, o);
        }
        if (qc == 0) {
            invs[qr]     = 1.0f / sum0;
            invs[qr + 8] = 1.0f / sum1;
        }
        __syncwarp();
        float o[4][4];
        #pragma unroll
        for (int jn = 0; jn < 4; jn++)
            #pragma unroll
            for (int c = 0; c < 4; c++) o[jn][c] = 0.f;
        #pragma unroll
        for (int ks2 = 0; ks2 < 7; ks2++) {
            const int kb = ks2*8;
            uint32_t a[4];
            a[0] = __float_as_uint(Pt[qr*AP_STR       + kb + qc    ]);
            a[1] = __float_as_uint(Pt[(qr + 8)*AP_STR + kb + qc    ]);
            a[2] = __float_as_uint(Pt[qr*AP_STR       + kb + qc + 4]);
            a[3] = __float_as_uint(Pt[(qr + 8)*AP_STR + kb + qc + 4]);
            #pragma unroll
            for (int jn = 0; jn < 4; jn++) {
                int n0 = jn*8 + qr;
                uint32_t b0 = __float_as_uint(vs[(size_t)(kb + qc    )*AV_STR + h32 + n0]);
                uint32_t b1 = __float_as_uint(vs[(size_t)(kb + qc + 4)*AV_STR + h32 + n0]);
                mma_tf32(o[jn], a, b0, b1);
            }
        }
        float i0 = invs[qr], i1 = invs[qr + 8];
        #pragma unroll
        for (int jn = 0; jn < 4; jn++) {
            int col = jn*8 + qc*2;
            if (v0) {
                float2 f; f.x = tf32r(o[jn][0]*i0); f.y = tf32r(o[jn][1]*i0);
                *(float2*)(obase + (size_t)r0*128 + col) = f;
            }
            if (v1) {
                float2 f; f.x = tf32r(o[jn][2]*i1); f.y = tf32r(o[jn][3]*i1);
                *(float2*)(obase + (size_t)r1*128 + col) = f;
            }
        }
        __syncwarp();
    }
}

// ---------------- TF32 tensor-core GEMM, cp.async double-buffered ---------
// C[M,Nd] = A[M,K] @ W[Nd,K]^T + epilogue. A and W are PRE-ROUNDED to tf32.
// Block tile 128x64, BK=32, 8 warps (4m x 2n), warp tile 32x32 (mf2 x nf4).
// Register-capped (launch_bounds 256,3) for 3 CTAs/SM = 24 warps.
#define TG_STG (192*36)             // u32 per stage (A 128 rows + B 64 rows, pad 36)
#define TG_SMEM (TG_STG*2*4)        // bytes, two stages = 55296

template<int EPI>
__global__ __launch_bounds__(256, 3) void tgemm_kernel(
    const float* __restrict__ A, const float* __restrict__ W,
    const float* __restrict__ bias, float* __restrict__ C,
    const float* __restrict__ aux, int M, int Nd, int K)
{
    extern __shared__ __align__(16) uint32_t dsm[];
    const int t    = threadIdx.x;
    const int warp = t >> 5;
    const int lane = t & 31;
    const int qr   = lane >> 2;
    const int qc   = lane & 3;
    const int wm   = warp & 3;    // m warp 0..3
    const int wn   = warp >> 2;   // n warp 0..1
    const int bm   = blockIdx.y * 128;
    const int bn   = blockIdx.x * 64;
    const int row0 = t >> 3;      // 0..31
    const int c4   = t & 7;

    const float* aptr = A + (size_t)(bm + row0)*K + c4*4;
    const float* wptr = W + (size_t)(bn + row0)*K + c4*4;
    const size_t rstr = (size_t)32 * K;

    uint32_t s_a = (uint32_t)__cvta_generic_to_shared(dsm);
    uint32_t s_b = s_a + 128*36*4;

    float acc[2][4][4] = {};

    const int iters = K >> 5;
    {
        #pragma unroll
        for (int l = 0; l < 4; l++)
            cp_async16(s_a + ((row0 + l*32)*36 + c4*4)*4, aptr + l*rstr);
        #pragma unroll
        for (int l = 0; l < 2; l++)
            cp_async16(s_b + ((row0 + l*32)*36 + c4*4)*4, wptr + l*rstr);
        cp_commit();
    }

    for (int it = 0; it < iters; it++) {
        if (it + 1 < iters) {
            uint32_t sa = s_a + ((it+1)&1)*TG_STG*4;
            uint32_t sb = s_b + ((it+1)&1)*TG_STG*4;
            const float* ap = aptr + (size_t)(it+1)*32;
            const float* wp = wptr + (size_t)(it+1)*32;
            #pragma unroll
            for (int l = 0; l < 4; l++)
                cp_async16(sa + ((row0 + l*32)*36 + c4*4)*4, ap + l*rstr);
            #pragma unroll
            for (int l = 0; l < 2; l++)
                cp_async16(sb + ((row0 + l*32)*36 + c4*4)*4, wp + l*rstr);
            cp_commit();
            cp_wait1();
        } else {
            cp_wait0();
        }
        __syncthreads();

        const uint32_t* As = dsm + (it&1)*TG_STG;
        const uint32_t* Bs = As + 128*36;
        #pragma unroll
        for (int ks = 0; ks < 4; ks++) {
            const int kb = ks * 8;
            uint32_t af[2][4];
            #pragma unroll
            for (int i = 0; i < 2; i++) {
                int m0 = wm*32 + i*16 + qr;
                af[i][0] = As[ m0     *36 + kb + qc    ];
                af[i][1] = As[(m0 + 8)*36 + kb + qc    ];
                af[i][2] = As[ m0     *36 + kb + qc + 4];
                af[i][3] = As[(m0 + 8)*36 + kb + qc + 4];
            }
            #pragma unroll
            for (int j = 0; j < 4; j++) {
                int n0 = wn*32 + j*8 + qr;
                uint32_t b0 = Bs[n0*36 + kb + qc    ];
                uint32_t b1 = Bs[n0*36 + kb + qc + 4];
                mma_tf32(acc[0][j], af[0], b0, b1);
                mma_tf32(acc[1][j], af[1], b0, b1);
            }
        }
        __syncthreads();
    }

    // ---- epilogue ----
    #pragma unroll
    for (int i = 0; i < 2; i++) {
        #pragma unroll
        for (int half = 0; half < 2; half++) {
            const int m = bm + wm*32 + i*16 + qr + half*8;
            size_t obase;
            if (EPI == 2) {
                int win = m / 49, nn = m - win*49;
                int bb = win >> 6, w = win & 63;
                int n7 = nn / 7;
                int pi = (w >> 3)*7 + n7;
                int pj = (w & 7)*7 + (nn - n7*7);
                int ii = pi + 3; if (ii >= 56) ii -= 56;
                int jj = pj + 3; if (jj >= 56) jj -= 56;
                obase = (((size_t)bb*56 + ii)*56 + jj)*128;
            } else {
                obase = (size_t)m * Nd;
            }
            #pragma unroll
            for (int j = 0; j < 4; j++) {
                const int n = bn + wn*32 + j*8 + qc*2;
                #pragma unroll
                for (int e = 0; e < 2; e++) {
                    const int nc = n + e;
                    float v = acc[i][j][half*2 + e];
                    if (EPI == 0) {
                        if (bias) v += bias[nc];
                        C[obase + nc] = v;
                    } else if (EPI == 1) {
                        v += bias[nc];
                        if (nc < 128) v *= 0.17677669529663687f;   // 1/sqrt(32)
                        C[obase + nc] = tf32r(v);
                    } else if (EPI == 2) {
                        v += bias[nc];
                        C[obase + nc] = v + aux[obase + nc];
                    } else if (EPI == 3) {
                        v += bias[nc];
                        C[obase + nc] = tf32r(0.5f * v * (1.0f + erff(v * 0.70710678118654752f)));
                    } else { // EPI == 4
                        v += bias[nc];
                        C[obase + nc] = v + aux[obase + nc];
                    }
                }
            }
        }
    }
}

// ---------------- launcher ----------------
extern "C" void kernel_launch(void* const* d_in, const int* in_sizes, int n_in,
                              void* d_out, int out_size)
{
    const float* x       = (const float*)d_in[0];
    const float* n1w     = (const float*)d_in[1];
    const float* n1b     = (const float*)d_in[2];
    const float* qkv_w   = (const float*)d_in[3];
    const float* qkv_b   = (const float*)d_in[4];
    const float* proj_w  = (const float*)d_in[5];
    const float* proj_b  = (const float*)d_in[6];
    const float* rpb     = (const float*)d_in[7];
    const float* n2w     = (const float*)d_in[8];
    const float* n2b     = (const float*)d_in[9];
    const float* fc1_w   = (const float*)d_in[10];
    const float* fc1_b   = (const float*)d_in[11];
    const float* fc2_w   = (const float*)d_in[12];
    const float* fc2_b   = (const float*)d_in[13];
    const float* mnw     = (const float*)d_in[14];
    const float* mnb     = (const float*)d_in[15];
    const float* merge_w = (const float*)d_in[16];
    const int*   rel_idx = (const int*)d_in[17];
    const float* amask   = (const float*)d_in[18];
    float* out = (float*)d_out;

    float *hw, *qkv, *o, *xres, *fc1, *wt;
    cudaGetSymbolAddress((void**)&hw,   g_hw);
    cudaGetSymbolAddress((void**)&qkv,  g_qkv);
    cudaGetSymbolAddress((void**)&o,    g_o);
    cudaGetSymbolAddress((void**)&xres, g_xres);
    cudaGetSymbolAddress((void**)&fc1,  g_fc1);
    cudaGetSymbolAddress((void**)&wt,   g_wt);

    // Dynamic-smem opt-in (REQUIRED: TG_SMEM/ATT_SMEM exceed the 48KB default)
    cudaFuncSetAttribute(tgemm_kernel<0>, cudaFuncAttributeMaxDynamicSharedMemorySize, TG_SMEM);
    cudaFuncSetAttribute(tgemm_kernel<1>, cudaFuncAttributeMaxDynamicSharedMemorySize, TG_SMEM);
    cudaFuncSetAttribute(tgemm_kernel<2>, cudaFuncAttributeMaxDynamicSharedMemorySize, TG_SMEM);
    cudaFuncSetAttribute(tgemm_kernel<3>, cudaFuncAttributeMaxDynamicSharedMemorySize, TG_SMEM);
    cudaFuncSetAttribute(tgemm_kernel<4>, cudaFuncAttributeMaxDynamicSharedMemorySize, TG_SMEM);
    cudaFuncSetAttribute(attn_kernel, cudaFuncAttributeMaxDynamicSharedMemorySize, ATT_SMEM);

    // 0. pre-round weights; build combined attention bias table
    round_w_kernel<<<WTOT/256, 256>>>(qkv_w, proj_w, fc1_w, fc2_w, merge_w);
    bias_prep_kernel<<<dim3(64, 4), 256>>>(rpb, rel_idx, amask);
    // 1. LN1 + roll + window partition (rounded)
    ln1_win_kernel<<<PIX/8, 256>>>(x, n1w, n1b);
    // 2. qkv GEMM (scale folded into q; rounded out)
    tgemm_kernel<1><<<dim3(6, M1_/128), 256, TG_SMEM>>>(hw, wt + WOFF_QKV, qkv_b, qkv, nullptr, M1_, 384, 128);
    // 3. windowed attention (tensor cores; rounded out)
    attn_kernel<<<4096, 128, ATT_SMEM>>>(qkv, o);
    // 4. proj GEMM + window-reverse + roll-back + residual -> xres (pixel layout)
    tgemm_kernel<2><<<dim3(2, M1_/128), 256, TG_SMEM>>>(o, wt + WOFF_PROJ, proj_b, xres, x, M1_, 128, 128);
    // 5. LN2: xres -> g_hw (rounded)
    ln2_kernel<<<PIX/8, 256>>>(n2w, n2b);
    // 6. fc1 GEMM + GELU (rounded out)
    tgemm_kernel<3><<<dim3(8, M1_/128), 256, TG_SMEM>>>(hw, wt + WOFF_FC1, fc1_b, fc1, nullptr, M1_, 512, 128);
    // 7. fc2 GEMM + residual (in place on xres)
    tgemm_kernel<4><<<dim3(2, M1_/128), 256, TG_SMEM>>>(fc1, wt + WOFF_FC2, fc2_b, xres, xres, M1_, 128, 512);
    // 8. patch-merge gather + LN(512): xres -> g_o (rounded, reuse as xm)
    merge_ln_kernel<<<M2_/8, 256>>>(mnw, mnb);
    // 9. merge GEMM -> output
    tgemm_kernel<0><<<dim3(4, M2_/128), 256, TG_SMEM>>>(o, wt + WOFF_MRG, nullptr, out, nullptr, M2_, 256, 512);
}

// round 10
// speedup vs baseline: 1.1382x; 1.1382x over previous
#include <cuda_runtime.h>
#include <cuda_fp16.h>
#include <math.h>
#include <stdint.h>

// ---------------- problem constants ----------------
#define BATCH 64
#define HS_   56
#define CC    128
#define NH_   4
#define HID_  512
#define PIX   (BATCH*HS_*HS_)      // 200704
#define M1_   PIX                  // window-token rows
#define M2_   (BATCH*28*28)        // 50176 merged rows

// weight scratch offsets (halves)
#define WOFF_QKV   0
#define WOFF_PROJ  49152
#define WOFF_FC1   65536
#define WOFF_FC2   131072
#define WOFF_MRG   196608
#define WTOT       327680

// ---------------- scratch (static device memory; allocation-free) ----------
__device__ __half g_hw[(size_t)M1_*CC];      // LN output (fp16)
__device__ __half g_qkv[(size_t)M1_*3*CC];   // qkv projections (fp16)
__device__ __half g_o[(size_t)M1_*CC];       // attn out / merged xm (fp16)
__device__ float  g_xres[(size_t)M1_*CC];    // residual stream (fp32, pixel layout)
__device__ __half g_fc1[(size_t)M1_*HID_];   // fc1+gelu output (fp16)
__device__ __half g_wt[WTOT];                // fp16 weights
__device__ float  g_bias[64*4*2401];         // combined rpb+mask per (wimg, head)

// ---------------- helpers ----------------
__device__ __forceinline__ uint32_t f2tf32(float x) {
    uint32_t r; asm("cvt.rna.tf32.f32 %0, %1;" : "=r"(r) : "f"(x)); return r;
}
__device__ __forceinline__ float tf32r(float x) { return __uint_as_float(f2tf32(x)); }
__device__ __forceinline__ void mma_tf32(float* c, const uint32_t* a, uint32_t b0, uint32_t b1) {
    asm volatile("mma.sync.aligned.m16n8k8.row.col.f32.tf32.tf32.f32 "
        "{%0,%1,%2,%3}, {%4,%5,%6,%7}, {%8,%9}, {%0,%1,%2,%3};\n"
        : "+f"(c[0]), "+f"(c[1]), "+f"(c[2]), "+f"(c[3])
        : "r"(a[0]), "r"(a[1]), "r"(a[2]), "r"(a[3]), "r"(b0), "r"(b1));
}
__device__ __forceinline__ void mma_f16(float* c, const uint32_t* a, uint32_t b0, uint32_t b1) {
    asm volatile("mma.sync.aligned.m16n8k16.row.col.f32.f16.f16.f32 "
        "{%0,%1,%2,%3}, {%4,%5,%6,%7}, {%8,%9}, {%0,%1,%2,%3};\n"
        : "+f"(c[0]), "+f"(c[1]), "+f"(c[2]), "+f"(c[3])
        : "r"(a[0]), "r"(a[1]), "r"(a[2]), "r"(a[3]), "r"(b0), "r"(b1));
}
__device__ __forceinline__ void cp_async16(uint32_t saddr, const void* gptr) {
    asm volatile("cp.async.cg.shared.global [%0], [%1], 16;\n" :: "r"(saddr), "l"(gptr));
}
__device__ __forceinline__ void cp_commit() { asm volatile("cp.async.commit_group;\n"); }
__device__ __forceinline__ void cp_wait1() { asm volatile("cp.async.wait_group 1;\n"); }
__device__ __forceinline__ void cp_wait0() { asm volatile("cp.async.wait_group 0;\n"); }

// ---------------- weight pre-convert to fp16 ----------------
__global__ void round_w_kernel(const float* __restrict__ qkv_w, const float* __restrict__ proj_w,
                               const float* __restrict__ fc1_w, const float* __restrict__ fc2_w,
                               const float* __restrict__ merge_w)
{
    int i = blockIdx.x * blockDim.x + threadIdx.x;
    float v;
    if      (i < WOFF_PROJ) v = qkv_w[i];
    else if (i < WOFF_FC1)  v = proj_w[i - WOFF_PROJ];
    else if (i < WOFF_FC2)  v = fc1_w[i - WOFF_FC1];
    else if (i < WOFF_MRG)  v = fc2_w[i - WOFF_FC2];
    else                    v = merge_w[i - WOFF_MRG];
    g_wt[i] = __float2half(v);
}

// ---------------- combined attention bias table: rpb[rel]+mask ------------
__global__ void bias_prep_kernel(const float* __restrict__ rpb,
                                 const int* __restrict__ rel,
                                 const float* __restrict__ mask)
{
    int wimg = blockIdx.x, h = blockIdx.y;
    float* dst = g_bias + ((size_t)wimg*4 + h)*2401;
    const float* msk = mask + (size_t)wimg*2401;
    for (int i = threadIdx.x; i < 2401; i += blockDim.x)
        dst[i] = rpb[rel[i]*4 + h] + msk[i];
}

// ---------------- helper: store 4 floats as 4 halves (8B) ----------------
__device__ __forceinline__ void st_half4(__half* p, float a, float b, float c, float d) {
    __half2 h0 = __floats2half2_rn(a, b);
    __half2 h1 = __floats2half2_rn(c, d);
    uint2 u;
    u.x = *(uint32_t*)&h0;
    u.y = *(uint32_t*)&h1;
    *(uint2*)p = u;
}

// ---------------- LN1 + roll(-3,-3) + window partition (fp16 out) --------
__global__ void ln1_win_kernel(const float* __restrict__ x,
                               const float* __restrict__ gw,
                               const float* __restrict__ gb)
{
    int warp = (blockIdx.x * blockDim.x + threadIdx.x) >> 5;
    int lane = threadIdx.x & 31;
    int b   = warp / 3136;
    int rem = warp - b * 3136;
    int i = rem / 56;
    int j = rem - i * 56;
    int si = i + 3; if (si >= 56) si -= 56;
    int sj = j + 3; if (sj >= 56) sj -= 56;
    float4 v = *(const float4*)(x + ((((size_t)b*56 + si)*56) + sj)*128 + lane*4);
    float s  = v.x + v.y + v.z + v.w;
    float ss = v.x*v.x + v.y*v.y + v.z*v.z + v.w*v.w;
    #pragma unroll
    for (int o = 16; o; o >>= 1) {
        s  += __shfl_xor_sync(0xffffffffu, s,  o);
        ss += __shfl_xor_sync(0xffffffffu, ss, o);
    }
    float mean = s * (1.0f/128.0f);
    float var  = ss * (1.0f/128.0f) - mean*mean;
    float rstd = rsqrtf(var + 1e-5f);
    float4 wv = *(const float4*)(gw + lane*4);
    float4 bv = *(const float4*)(gb + lane*4);
    int i7 = i / 7, j7 = j / 7;
    int widx = i7*8 + j7;
    int n    = (i - i7*7)*7 + (j - j7*7);
    size_t row = (size_t)(b*64 + widx)*49 + n;
    st_half4(g_hw + row*128 + lane*4,
             (v.x - mean)*rstd*wv.x + bv.x,
             (v.y - mean)*rstd*wv.y + bv.y,
             (v.z - mean)*rstd*wv.z + bv.z,
             (v.w - mean)*rstd*wv.w + bv.w);
}

// ---------------- LN2 (pixel layout): g_xres -> g_hw (fp16) ---------------
__global__ void ln2_kernel(const float* __restrict__ gw, const float* __restrict__ gb)
{
    int warp = (blockIdx.x * blockDim.x + threadIdx.x) >> 5;
    int lane = threadIdx.x & 31;
    float4 v = *(const float4*)(g_xres + (size_t)warp*128 + lane*4);
    float s  = v.x + v.y + v.z + v.w;
    float ss = v.x*v.x + v.y*v.y + v.z*v.z + v.w*v.w;
    #pragma unroll
    for (int o = 16; o; o >>= 1) {
        s  += __shfl_xor_sync(0xffffffffu, s,  o);
        ss += __shfl_xor_sync(0xffffffffu, ss, o);
    }
    float mean = s * (1.0f/128.0f);
    float var  = ss * (1.0f/128.0f) - mean*mean;
    float rstd = rsqrtf(var + 1e-5f);
    float4 wv = *(const float4*)(gw + lane*4);
    float4 bv = *(const float4*)(gb + lane*4);
    st_half4(g_hw + (size_t)warp*128 + lane*4,
             (v.x - mean)*rstd*wv.x + bv.x,
             (v.y - mean)*rstd*wv.y + bv.y,
             (v.z - mean)*rstd*wv.z + bv.z,
             (v.w - mean)*rstd*wv.w + bv.w);
}

// ---------------- patch-merge gather + LN(512): g_xres -> g_o (fp16) ------
__global__ void merge_ln_kernel(const float* __restrict__ gw, const float* __restrict__ gb)
{
    int warp = (blockIdx.x * blockDim.x + threadIdx.x) >> 5;
    int lane = threadIdx.x & 31;
    int b   = warp / 784;
    int rem = warp - b * 784;
    int i2 = rem / 28;
    int j2 = rem - i2 * 28;
    int i0 = 2*i2, j0 = 2*j2;
    const float* p0 = g_xres + (((size_t)b*56 + i0    )*56 + j0    )*128;
    const float* p1 = g_xres + (((size_t)b*56 + i0 + 1)*56 + j0    )*128;
    const float* p2 = g_xres + (((size_t)b*56 + i0    )*56 + j0 + 1)*128;
    const float* p3 = g_xres + (((size_t)b*56 + i0 + 1)*56 + j0 + 1)*128;
    float4 v[4];
    v[0] = *(const float4*)(p0 + lane*4);
    v[1] = *(const float4*)(p1 + lane*4);
    v[2] = *(const float4*)(p2 + lane*4);
    v[3] = *(const float4*)(p3 + lane*4);
    float s = 0.f, ss = 0.f;
    #pragma unroll
    for (int q = 0; q < 4; q++) {
        s  += v[q].x + v[q].y + v[q].z + v[q].w;
        ss += v[q].x*v[q].x + v[q].y*v[q].y + v[q].z*v[q].z + v[q].w*v[q].w;
    }
    #pragma unroll
    for (int o = 16; o; o >>= 1) {
        s  += __shfl_xor_sync(0xffffffffu, s,  o);
        ss += __shfl_xor_sync(0xffffffffu, ss, o);
    }
    float mean = s * (1.0f/512.0f);
    float var  = ss * (1.0f/512.0f) - mean*mean;
    float rstd = rsqrtf(var + 1e-5f);
    __half* out = g_o + (size_t)warp*512;
    #pragma unroll
    for (int q = 0; q < 4; q++) {
        int c = q*128 + lane*4;
        float4 wv = *(const float4*)(gw + c);
        float4 bv = *(const float4*)(gb + c);
        st_half4(out + c,
                 (v[q].x - mean)*rstd*wv.x + bv.x,
                 (v[q].y - mean)*rstd*wv.y + bv.y,
                 (v[q].z - mean)*rstd*wv.z + bv.z,
                 (v[q].w - mean)*rstd*wv.w + bv.w);
    }
}

// ---------------- MMA attention: block = one window, warp = one head ------
// fp16 I/O, tf32 internals (unchanged from round 6, proven correct).
#define AQ_STR 132
#define AK_STR 132
#define AV_STR 136
#define AP_STR 60
#define AOFF_K (64*AQ_STR)                  // 8448
#define AOFF_V (AOFF_K + 56*AK_STR)         // 15840
#define AOFF_P (AOFF_V + 56*AV_STR)         // 23456
#define AOFF_I (AOFF_P + 4*16*AP_STR)       // 27296
#define ATT_SMEM ((AOFF_I + 4*16)*4)        // 109440 bytes

__global__ __launch_bounds__(128) void attn_kernel(
    const __half* __restrict__ qkv, __half* __restrict__ outp)
{
    extern __shared__ float sm[];
    float* qs = sm;
    float* ks = sm + AOFF_K;
    float* vs = sm + AOFF_V;
    const int t    = threadIdx.x;
    const int warp = t >> 5;
    const int lane = t & 31;
    const int win  = blockIdx.x;
    float* Pt   = sm + AOFF_P + warp*16*AP_STR;
    float* invs = sm + AOFF_I + warp*16;

    const __half* base = qkv + (size_t)win*49*384;
    for (int idx = t; idx < 49*48; idx += 128) {
        int row = idx / 48;
        int sub = idx - row*48;
        int kind = sub >> 4;        // 0=q 1=k 2=v
        int c8 = sub & 15;          // 8-half chunk
        uint4 hv = *(const uint4*)(base + (size_t)row*384 + kind*128 + c8*8);
        const __half2* hp = (const __half2*)&hv;
        float* dst = (kind == 0 ? qs + row*AQ_STR :
                      kind == 1 ? ks + row*AK_STR : vs + row*AV_STR) + c8*8;
        float2 f0 = __half22float2(hp[0]);
        float2 f1 = __half22float2(hp[1]);
        float2 f2 = __half22float2(hp[2]);
        float2 f3 = __half22float2(hp[3]);
        float4 o0; o0.x = f0.x; o0.y = f0.y; o0.z = f1.x; o0.w = f1.y;
        float4 o1; o1.x = f2.x; o1.y = f2.y; o1.z = f3.x; o1.w = f3.y;
        *(float4*)dst = o0;
        *(float4*)(dst + 4) = o1;
    }
    for (int idx = t; idx < 7*AV_STR; idx += 128) {
        int r = idx / AV_STR, c = idx - r*AV_STR;
        vs[(49+r)*AV_STR + c] = 0.f;
        if (c < AK_STR) ks[(49+r)*AK_STR + c] = 0.f;
    }
    __syncthreads();

    const int h   = warp;
    const int qr  = lane >> 2;
    const int qc  = lane & 3;
    const int h32 = h * 32;
    const float* comb = g_bias + (size_t)((win & 63)*4 + h)*2401;
    __half* obase = outp + (size_t)win*49*128 + h32;

    for (int mt = 0; mt < 4; mt++) {
        const int r0 = mt*16 + qr;
        const int r1 = r0 + 8;
        float s[7][4];
        #pragma unroll
        for (int jn = 0; jn < 7; jn++)
            #pragma unroll
            for (int c = 0; c < 4; c++) s[jn][c] = 0.f;
        #pragma unroll
        for (int kb = 0; kb < 32; kb += 8) {
            uint32_t a[4];
            a[0] = __float_as_uint(qs[(size_t)r0*AQ_STR + h32 + kb + qc    ]);
            a[1] = __float_as_uint(qs[(size_t)r1*AQ_STR + h32 + kb + qc    ]);
            a[2] = __float_as_uint(qs[(size_t)r0*AQ_STR + h32 + kb + qc + 4]);
            a[3] = __float_as_uint(qs[(size_t)r1*AQ_STR + h32 + kb + qc + 4]);
            #pragma unroll
            for (int jn = 0; jn < 7; jn++) {
                int n0 = jn*8 + qr;
                uint32_t b0 = __float_as_uint(ks[(size_t)n0*AK_STR + h32 + kb + qc    ]);
                uint32_t b1 = __float_as_uint(ks[(size_t)n0*AK_STR + h32 + kb + qc + 4]);
                mma_tf32(s[jn], a, b0, b1);
            }
        }
        const bool v0 = (r0 < 49), v1 = (r1 < 49);
        float mx0 = -1e30f, mx1 = -1e30f;
        #pragma unroll
        for (int jn = 0; jn < 7; jn++) {
            #pragma unroll
            for (int e = 0; e < 2; e++) {
                int col = jn*8 + qc*2 + e;
                if (col < 49) {
                    if (v0) s[jn][e]     += comb[r0*49 + col];
                    if (v1) s[jn][2 + e] += comb[r1*49 + col];
                } else {
                    s[jn][e] = -1e30f; s[jn][2 + e] = -1e30f;
                }
                mx0 = fmaxf(mx0, s[jn][e]);
                mx1 = fmaxf(mx1, s[jn][2 + e]);
            }
        }
        #pragma unroll
        for (int o = 1; o <= 2; o <<= 1) {
            mx0 = fmaxf(mx0, __shfl_xor_sync(0xffffffffu, mx0, o));
            mx1 = fmaxf(mx1, __shfl_xor_sync(0xffffffffu, mx1, o));
        }
        float sum0 = 0.f, sum1 = 0.f;
        #pragma unroll
        for (int jn = 0; jn < 7; jn++) {
            #pragma unroll
            for (int e = 0; e < 2; e++) {
                int col = jn*8 + qc*2 + e;
                float e0 = __expf(s[jn][e]     - mx0);
                float e1 = __expf(s[jn][2 + e] - mx1);
                sum0 += e0; sum1 += e1;
                Pt[qr*AP_STR       + col] = tf32r(e0);
                Pt[(qr + 8)*AP_STR + col] = tf32r(e1);
            }
        }
        #pragma unroll
        for (int o = 1; o <= 2; o <<= 1) {
            sum0 += __shfl_xor_sync(0xffffffffu, sum0, o);
            sum1 += __shfl_xor_sync(0xffffffffu, sum1, o);
        }
        if (qc == 0) {
            invs[qr]     = 1.0f / sum0;
            invs[qr + 8] = 1.0f / sum1;
        }
        __syncwarp();
        float o[4][4];
        #pragma unroll
        for (int jn = 0; jn < 4; jn++)
            #pragma unroll
            for (int c = 0; c < 4; c++) o[jn][c] = 0.f;
        #pragma unroll
        for (int ks2 = 0; ks2 < 7; ks2++) {
            const int kb = ks2*8;
            uint32_t a[4];
            a[0] = __float_as_uint(Pt[qr*AP_STR       + kb + qc    ]);
            a[1] = __float_as_uint(Pt[(qr + 8)*AP_STR + kb + qc    ]);
            a[2] = __float_as_uint(Pt[qr*AP_STR       + kb + qc + 4]);
            a[3] = __float_as_uint(Pt[(qr + 8)*AP_STR + kb + qc + 4]);
            #pragma unroll
            for (int jn = 0; jn < 4; jn++) {
                int n0 = jn*8 + qr;
                uint32_t b0 = __float_as_uint(vs[(size_t)(kb + qc    )*AV_STR + h32 + n0]);
                uint32_t b1 = __float_as_uint(vs[(size_t)(kb + qc + 4)*AV_STR + h32 + n0]);
                mma_tf32(o[jn], a, b0, b1);
            }
        }
        float i0 = invs[qr], i1 = invs[qr + 8];
        #pragma unroll
        for (int jn = 0; jn < 4; jn++) {
            int col = jn*8 + qc*2;
            if (v0) {
                __half2 f = __floats2half2_rn(o[jn][0]*i0, o[jn][1]*i0);
                *(__half2*)(obase + (size_t)r0*128 + col) = f;
            }
            if (v1) {
                __half2 f = __floats2half2_rn(o[jn][2]*i1, o[jn][3]*i1);
                *(__half2*)(obase + (size_t)r1*128 + col) = f;
            }
        }
        __syncwarp();
    }
}

// ---------------- FP16 tensor-core GEMM, cp.async double-buffered ---------
// C[M,Nd] = A[M,K] @ W[Nd,K]^T + epilogue. A and W are fp16.
// Block tile 128x128, BK=32, 8 warps (4m x 2n), warp tile 32x64 (mf2 x nf8).
// m16n8k16: 2 k-steps per BK (half the instructions of the tf32 path).
// Smem rows padded to 80B (20 half2) -> cp.async 16B-aligned, frag loads
// conflict-free (bank = (20*qr + qc) mod 32, all distinct).
// EPI 0: plain fp32 store (no bias for merge)
// EPI 1: +bias; cols<128 scaled 1/sqrt(32); fp16 store
// EPI 2: +bias; window-reverse + roll(+3,+3) scatter; + residual aux; fp32
// EPI 3: +bias; exact GELU; fp16 store
// EPI 4: +bias; + residual aux; fp32 (in place on g_xres)
#define TG_STG_BYTES (256*80)       // one stage: (128 A + 128 B rows) * 80B
#define TG_SMEM (TG_STG_BYTES*2)    // 40960 bytes

template<int EPI>
__global__ __launch_bounds__(256, 2) void tgemm_kernel(
    const __half* __restrict__ A, const __half* __restrict__ W,
    const float* __restrict__ bias, void* __restrict__ Cv,
    const float* __restrict__ aux, int M, int Nd, int K)
{
    extern __shared__ __align__(16) char dsm[];
    const int t    = threadIdx.x;
    const int warp = t >> 5;
    const int lane = t & 31;
    const int qr   = lane >> 2;
    const int qc   = lane & 3;
    const int wm   = warp & 3;    // m warp 0..3
    const int wn   = warp >> 2;   // n warp 0..1
    const int bm   = blockIdx.y * 128;
    const int bn   = blockIdx.x * 128;
    const int rowX = t >> 2;      // 0..63
    const int cX   = t & 3;       // 8-half chunk within 32-half row slice

    const __half* aG = A + (size_t)(bm + rowX)*K + cX*8;
    const __half* wG = W + (size_t)(bn + rowX)*K + cX*8;
    const size_t r64 = (size_t)64 * K;

    uint32_t s0 = (uint32_t)__cvta_generic_to_shared(dsm);
    const uint32_t sA = s0 + rowX*80 + cX*16;
    const uint32_t sB = sA + 128*80;

    float acc[2][8][4] = {};
    const int iters = K >> 5;

    // prologue: stage 0
    cp_async16(sA,         aG);
    cp_async16(sA + 64*80, aG + r64);
    cp_async16(sB,         wG);
    cp_async16(sB + 64*80, wG + r64);
    cp_commit();

    for (int it = 0; it < iters; it++) {
        if (it + 1 < iters) {
            uint32_t off = ((it+1)&1)*TG_STG_BYTES;
            const __half* ag = aG + (size_t)(it+1)*32;
            const __half* wg = wG + (size_t)(it+1)*32;
            cp_async16(sA + off,         ag);
            cp_async16(sA + off + 64*80, ag + r64);
            cp_async16(sB + off,         wg);
            cp_async16(sB + off + 64*80, wg + r64);
            cp_commit();
            cp_wait1();
        } else {
            cp_wait0();
        }
        __syncthreads();

        const uint32_t* As2 = (const uint32_t*)(dsm + (it&1)*TG_STG_BYTES);  // half2 view, row stride 20
        const uint32_t* Bs2 = As2 + 128*20;
        #pragma unroll
        for (int ks = 0; ks < 2; ks++) {
            const int kb = ks * 8;   // half2 units (k = 16 per step)
            uint32_t af[2][4];
            #pragma unroll
            for (int i = 0; i < 2; i++) {
                int m0 = wm*32 + i*16 + qr;
                af[i][0] = As2[ m0     *20 + kb + qc    ];
                af[i][1] = As2[(m0 + 8)*20 + kb + qc    ];
                af[i][2] = As2[ m0     *20 + kb + qc + 4];
                af[i][3] = As2[(m0 + 8)*20 + kb + qc + 4];
            }
            #pragma unroll
            for (int j = 0; j < 8; j++) {
                int n0 = wn*64 + j*8 + qr;
                uint32_t b0 = Bs2[n0*20 + kb + qc    ];
                uint32_t b1 = Bs2[n0*20 + kb + qc + 4];
                mma_f16(acc[0][j], af[0], b0, b1);
                mma_f16(acc[1][j], af[1], b0, b1);
            }
        }
        __syncthreads();
    }

    // ---- epilogue ----
    float*  Cf = (float*)Cv;
    __half* Ch = (__half*)Cv;
    #pragma unroll
    for (int i = 0; i < 2; i++) {
        #pragma unroll
        for (int half_ = 0; half_ < 2; half_++) {
            const int m = bm + wm*32 + i*16 + qr + half_*8;
            size_t obase;
            if (EPI == 2) {
                int win = m / 49, nn = m - win*49;
                int bb = win >> 6, w = win & 63;
                int n7 = nn / 7;
                int pi = (w >> 3)*7 + n7;
                int pj = (w & 7)*7 + (nn - n7*7);
                int ii = pi + 3; if (ii >= 56) ii -= 56;
                int jj = pj + 3; if (jj >= 56) jj -= 56;
                obase = (((size_t)bb*56 + ii)*56 + jj)*128;
            } else {
                obase = (size_t)m * Nd;
            }
            #pragma unroll
            for (int j = 0; j < 8; j++) {
                const int n = bn + wn*64 + j*8 + qc*2;
                #pragma unroll
                for (int e = 0; e < 2; e++) {
                    const int nc = n + e;
                    float v = acc[i][j][half_*2 + e];
                    if (EPI == 0) {
                        Cf[obase + nc] = v;
                    } else if (EPI == 1) {
                        v += bias[nc];
                        if (nc < 128) v *= 0.17677669529663687f;   // 1/sqrt(32)
                        Ch[obase + nc] = __float2half(v);
                    } else if (EPI == 2) {
                        v += bias[nc];
                        Cf[obase + nc] = v + aux[obase + nc];
                    } else if (EPI == 3) {
                        v += bias[nc];
                        Ch[obase + nc] = __float2half(0.5f * v * (1.0f + erff(v * 0.70710678118654752f)));
                    } else { // EPI == 4
                        v += bias[nc];
                        Cf[obase + nc] = v + aux[obase + nc];
                    }
                }
            }
        }
    }
}

// ---------------- launcher ----------------
extern "C" void kernel_launch(void* const* d_in, const int* in_sizes, int n_in,
                              void* d_out, int out_size)
{
    const float* x       = (const float*)d_in[0];
    const float* n1w     = (const float*)d_in[1];
    const float* n1b     = (const float*)d_in[2];
    const float* qkv_w   = (const float*)d_in[3];
    const float* qkv_b   = (const float*)d_in[4];
    const float* proj_w  = (const float*)d_in[5];
    const float* proj_b  = (const float*)d_in[6];
    const float* rpb     = (const float*)d_in[7];
    const float* n2w     = (const float*)d_in[8];
    const float* n2b     = (const float*)d_in[9];
    const float* fc1_w   = (const float*)d_in[10];
    const float* fc1_b   = (const float*)d_in[11];
    const float* fc2_w   = (const float*)d_in[12];
    const float* fc2_b   = (const float*)d_in[13];
    const float* mnw     = (const float*)d_in[14];
    const float* mnb     = (const float*)d_in[15];
    const float* merge_w = (const float*)d_in[16];
    const int*   rel_idx = (const int*)d_in[17];
    const float* amask   = (const float*)d_in[18];
    float* out = (float*)d_out;

    __half *hw, *qkv, *o, *fc1, *wt;
    float *xres;
    cudaGetSymbolAddress((void**)&hw,   g_hw);
    cudaGetSymbolAddress((void**)&qkv,  g_qkv);
    cudaGetSymbolAddress((void**)&o,    g_o);
    cudaGetSymbolAddress((void**)&xres, g_xres);
    cudaGetSymbolAddress((void**)&fc1,  g_fc1);
    cudaGetSymbolAddress((void**)&wt,   g_wt);

    cudaFuncSetAttribute(tgemm_kernel<0>, cudaFuncAttributeMaxDynamicSharedMemorySize, TG_SMEM);
    cudaFuncSetAttribute(tgemm_kernel<1>, cudaFuncAttributeMaxDynamicSharedMemorySize, TG_SMEM);
    cudaFuncSetAttribute(tgemm_kernel<2>, cudaFuncAttributeMaxDynamicSharedMemorySize, TG_SMEM);
    cudaFuncSetAttribute(tgemm_kernel<3>, cudaFuncAttributeMaxDynamicSharedMemorySize, TG_SMEM);
    cudaFuncSetAttribute(tgemm_kernel<4>, cudaFuncAttributeMaxDynamicSharedMemorySize, TG_SMEM);
    cudaFuncSetAttribute(attn_kernel, cudaFuncAttributeMaxDynamicSharedMemorySize, ATT_SMEM);

    // 0. pre-convert weights to fp16; build combined attention bias table
    round_w_kernel<<<WTOT/256, 256>>>(qkv_w, proj_w, fc1_w, fc2_w, merge_w);
    bias_prep_kernel<<<dim3(64, 4), 256>>>(rpb, rel_idx, amask);
    // 1. LN1 + roll + window partition (fp16 out)
    ln1_win_kernel<<<PIX/8, 256>>>(x, n1w, n1b);
    // 2. qkv GEMM (scale folded into q; fp16 out)
    tgemm_kernel<1><<<dim3(3, M1_/128), 256, TG_SMEM>>>(hw, wt + WOFF_QKV, qkv_b, qkv, nullptr, M1_, 384, 128);
    // 3. windowed attention (tensor cores; fp16 out)
    attn_kernel<<<4096, 128, ATT_SMEM>>>(qkv, o);
    // 4. proj GEMM + window-reverse + roll-back + residual -> xres (fp32, pixel layout)
    tgemm_kernel<2><<<dim3(1, M1_/128), 256, TG_SMEM>>>(o, wt + WOFF_PROJ, proj_b, xres, x, M1_, 128, 128);
    // 5. LN2: xres -> g_hw (fp16)
    ln2_kernel<<<PIX/8, 256>>>(n2w, n2b);
    // 6. fc1 GEMM + GELU (fp16 out)
    tgemm_kernel<3><<<dim3(4, M1_/128), 256, TG_SMEM>>>(hw, wt + WOFF_FC1, fc1_b, fc1, nullptr, M1_, 512, 128);
    // 7. fc2 GEMM + residual (fp32, in place on xres)
    tgemm_kernel<4><<<dim3(1, M1_/128), 256, TG_SMEM>>>(fc1, wt + WOFF_FC2, fc2_b, xres, xres, M1_, 128, 512);
    // 8. patch-merge gather + LN(512): xres -> g_o (fp16, reuse as xm)
    merge_ln_kernel<<<M2_/8, 256>>>(mnw, mnb);
    // 9. merge GEMM -> output (fp32)
    tgemm_kernel<0><<<dim3(2, M2_/128), 256, TG_SMEM>>>(o, wt + WOFF_MRG, nullptr, out, nullptr, M2_, 256, 512);
}

// round 12
// speedup vs baseline: 1.4846x; 1.3043x over previous
#include <cuda_runtime.h>
#include <cuda_fp16.h>
#include <math.h>
#include <stdint.h>

// ---------------- problem constants ----------------
#define BATCH 64
#define HS_   56
#define CC    128
#define NH_   4
#define HID_  512
#define PIX   (BATCH*HS_*HS_)      // 200704
#define M1_   PIX                  // window-token rows
#define M2_   (BATCH*28*28)        // 50176 merged rows

// weight scratch offsets (halves)
#define WOFF_QKV   0
#define WOFF_PROJ  49152
#define WOFF_FC1   65536
#define WOFF_FC2   131072
#define WOFF_MRG   196608
#define WTOT       327680

// ---------------- scratch (static device memory; allocation-free) ----------
__device__ __half g_hw[(size_t)M1_*CC];      // LN output (fp16)
__device__ __half g_qkv[(size_t)M1_*3*CC];   // qkv projections (fp16)
__device__ __half g_o[(size_t)M1_*CC];       // attn out / merged xm (fp16)
__device__ float  g_xres[(size_t)M1_*CC];    // residual stream (fp32, pixel layout)
__device__ __half g_fc1[(size_t)M1_*HID_];   // fc1+gelu output (fp16)
__device__ __half g_wt[WTOT];                // fp16 weights
__device__ float  g_bias[64*4*2401];         // combined rpb+mask per (wimg, head)

// ---------------- helpers ----------------
__device__ __forceinline__ uint32_t f2tf32(float x) {
    uint32_t r; asm("cvt.rna.tf32.f32 %0, %1;" : "=r"(r) : "f"(x)); return r;
}
__device__ __forceinline__ float tf32r(float x) { return __uint_as_float(f2tf32(x)); }
__device__ __forceinline__ void mma_tf32(float* c, const uint32_t* a, uint32_t b0, uint32_t b1) {
    asm volatile("mma.sync.aligned.m16n8k8.row.col.f32.tf32.tf32.f32 "
        "{%0,%1,%2,%3}, {%4,%5,%6,%7}, {%8,%9}, {%0,%1,%2,%3};\n"
        : "+f"(c[0]), "+f"(c[1]), "+f"(c[2]), "+f"(c[3])
        : "r"(a[0]), "r"(a[1]), "r"(a[2]), "r"(a[3]), "r"(b0), "r"(b1));
}
__device__ __forceinline__ void mma_f16(float* c, const uint32_t* a, uint32_t b0, uint32_t b1) {
    asm volatile("mma.sync.aligned.m16n8k16.row.col.f32.f16.f16.f32 "
        "{%0,%1,%2,%3}, {%4,%5,%6,%7}, {%8,%9}, {%0,%1,%2,%3};\n"
        : "+f"(c[0]), "+f"(c[1]), "+f"(c[2]), "+f"(c[3])
        : "r"(a[0]), "r"(a[1]), "r"(a[2]), "r"(a[3]), "r"(b0), "r"(b1));
}
__device__ __forceinline__ void cp_async16(uint32_t saddr, const void* gptr) {
    asm volatile("cp.async.cg.shared.global [%0], [%1], 16;\n" :: "r"(saddr), "l"(gptr));
}
__device__ __forceinline__ void cp_commit() { asm volatile("cp.async.commit_group;\n"); }
__device__ __forceinline__ void cp_wait2() { asm volatile("cp.async.wait_group 2;\n"); }
__device__ __forceinline__ void cp_wait1() { asm volatile("cp.async.wait_group 1;\n"); }
__device__ __forceinline__ void cp_wait0() { asm volatile("cp.async.wait_group 0;\n"); }

// ---------------- weight pre-convert to fp16 ----------------
__global__ void round_w_kernel(const float* __restrict__ qkv_w, const float* __restrict__ proj_w,
                               const float* __restrict__ fc1_w, const float* __restrict__ fc2_w,
                               const float* __restrict__ merge_w)
{
    int i = blockIdx.x * blockDim.x + threadIdx.x;
    float v;
    if      (i < WOFF_PROJ) v = qkv_w[i];
    else if (i < WOFF_FC1)  v = proj_w[i - WOFF_PROJ];
    else if (i < WOFF_FC2)  v = fc1_w[i - WOFF_FC1];
    else if (i < WOFF_MRG)  v = fc2_w[i - WOFF_FC2];
    else                    v = merge_w[i - WOFF_MRG];
    g_wt[i] = __float2half(v);
}

// ---------------- combined attention bias table: rpb[rel]+mask ------------
__global__ void bias_prep_kernel(const float* __restrict__ rpb,
                                 const int* __restrict__ rel,
                                 const float* __restrict__ mask)
{
    int wimg = blockIdx.x, h = blockIdx.y;
    float* dst = g_bias + ((size_t)wimg*4 + h)*2401;
    const float* msk = mask + (size_t)wimg*2401;
    for (int i = threadIdx.x; i < 2401; i += blockDim.x)
        dst[i] = rpb[rel[i]*4 + h] + msk[i];
}

// ---------------- helper: store 4 floats as 4 halves (8B) ----------------
__device__ __forceinline__ void st_half4(__half* p, float a, float b, float c, float d) {
    __half2 h0 = __floats2half2_rn(a, b);
    __half2 h1 = __floats2half2_rn(c, d);
    uint2 u;
    u.x = *(uint32_t*)&h0;
    u.y = *(uint32_t*)&h1;
    *(uint2*)p = u;
}

// ---------------- LN1 + roll(-3,-3) + window partition (fp16 out) --------
__global__ void ln1_win_kernel(const float* __restrict__ x,
                               const float* __restrict__ gw,
                               const float* __restrict__ gb)
{
    int warp = (blockIdx.x * blockDim.x + threadIdx.x) >> 5;
    int lane = threadIdx.x & 31;
    int b   = warp / 3136;
    int rem = warp - b * 3136;
    int i = rem / 56;
    int j = rem - i * 56;
    int si = i + 3; if (si >= 56) si -= 56;
    int sj = j + 3; if (sj >= 56) sj -= 56;
    float4 v = *(const float4*)(x + ((((size_t)b*56 + si)*56) + sj)*128 + lane*4);
    float s  = v.x + v.y + v.z + v.w;
    float ss = v.x*v.x + v.y*v.y + v.z*v.z + v.w*v.w;
    #pragma unroll
    for (int o = 16; o; o >>= 1) {
        s  += __shfl_xor_sync(0xffffffffu, s,  o);
        ss += __shfl_xor_sync(0xffffffffu, ss, o);
    }
    float mean = s * (1.0f/128.0f);
    float var  = ss * (1.0f/128.0f) - mean*mean;
    float rstd = rsqrtf(var + 1e-5f);
    float4 wv = *(const float4*)(gw + lane*4);
    float4 bv = *(const float4*)(gb + lane*4);
    int i7 = i / 7, j7 = j / 7;
    int widx = i7*8 + j7;
    int n    = (i - i7*7)*7 + (j - j7*7);
    size_t row = (size_t)(b*64 + widx)*49 + n;
    st_half4(g_hw + row*128 + lane*4,
             (v.x - mean)*rstd*wv.x + bv.x,
             (v.y - mean)*rstd*wv.y + bv.y,
             (v.z - mean)*rstd*wv.z + bv.z,
             (v.w - mean)*rstd*wv.w + bv.w);
}

// ---------------- LN2 (pixel layout): g_xres -> g_hw (fp16) ---------------
__global__ void ln2_kernel(const float* __restrict__ gw, const float* __restrict__ gb)
{
    int warp = (blockIdx.x * blockDim.x + threadIdx.x) >> 5;
    int lane = threadIdx.x & 31;
    float4 v = *(const float4*)(g_xres + (size_t)warp*128 + lane*4);
    float s  = v.x + v.y + v.z + v.w;
    float ss = v.x*v.x + v.y*v.y + v.z*v.z + v.w*v.w;
    #pragma unroll
    for (int o = 16; o; o >>= 1) {
        s  += __shfl_xor_sync(0xffffffffu, s,  o);
        ss += __shfl_xor_sync(0xffffffffu, ss, o);
    }
    float mean = s * (1.0f/128.0f);
    float var  = ss * (1.0f/128.0f) - mean*mean;
    float rstd = rsqrtf(var + 1e-5f);
    float4 wv = *(const float4*)(gw + lane*4);
    float4 bv = *(const float4*)(gb + lane*4);
    st_half4(g_hw + (size_t)warp*128 + lane*4,
             (v.x - mean)*rstd*wv.x + bv.x,
             (v.y - mean)*rstd*wv.y + bv.y,
             (v.z - mean)*rstd*wv.z + bv.z,
             (v.w - mean)*rstd*wv.w + bv.w);
}

// ---------------- patch-merge gather + LN(512): g_xres -> g_o (fp16) ------
__global__ void merge_ln_kernel(const float* __restrict__ gw, const float* __restrict__ gb)
{
    int warp = (blockIdx.x * blockDim.x + threadIdx.x) >> 5;
    int lane = threadIdx.x & 31;
    int b   = warp / 784;
    int rem = warp - b * 784;
    int i2 = rem / 28;
    int j2 = rem - i2 * 28;
    int i0 = 2*i2, j0 = 2*j2;
    const float* p0 = g_xres + (((size_t)b*56 + i0    )*56 + j0    )*128;
    const float* p1 = g_xres + (((size_t)b*56 + i0 + 1)*56 + j0    )*128;
    const float* p2 = g_xres + (((size_t)b*56 + i0    )*56 + j0 + 1)*128;
    const float* p3 = g_xres + (((size_t)b*56 + i0 + 1)*56 + j0 + 1)*128;
    float4 v[4];
    v[0] = *(const float4*)(p0 + lane*4);
    v[1] = *(const float4*)(p1 + lane*4);
    v[2] = *(const float4*)(p2 + lane*4);
    v[3] = *(const float4*)(p3 + lane*4);
    float s = 0.f, ss = 0.f;
    #pragma unroll
    for (int q = 0; q < 4; q++) {
        s  += v[q].x + v[q].y + v[q].z + v[q].w;
        ss += v[q].x*v[q].x + v[q].y*v[q].y + v[q].z*v[q].z + v[q].w*v[q].w;
    }
    #pragma unroll
    for (int o = 16; o; o >>= 1) {
        s  += __shfl_xor_sync(0xffffffffu, s,  o);
        ss += __shfl_xor_sync(0xffffffffu, ss, o);
    }
    float mean = s * (1.0f/512.0f);
    float var  = ss * (1.0f/512.0f) - mean*mean;
    float rstd = rsqrtf(var + 1e-5f);
    __half* out = g_o + (size_t)warp*512;
    #pragma unroll
    for (int q = 0; q < 4; q++) {
        int c = q*128 + lane*4;
        float4 wv = *(const float4*)(gw + c);
        float4 bv = *(const float4*)(gb + c);
        st_half4(out + c,
                 (v[q].x - mean)*rstd*wv.x + bv.x,
                 (v[q].y - mean)*rstd*wv.y + bv.y,
                 (v[q].z - mean)*rstd*wv.z + bv.z,
                 (v[q].w - mean)*rstd*wv.w + bv.w);
    }
}

// ---------------- MMA attention: block = one window, warp = one head ------
// fp16 I/O, tf32 internals (unchanged, proven correct).
#define AQ_STR 132
#define AK_STR 132
#define AV_STR 136
#define AP_STR 60
#define AOFF_K (64*AQ_STR)                  // 8448
#define AOFF_V (AOFF_K + 56*AK_STR)         // 15840
#define AOFF_P (AOFF_V + 56*AV_STR)         // 23456
#define AOFF_I (AOFF_P + 4*16*AP_STR)       // 27296
#define ATT_SMEM ((AOFF_I + 4*16)*4)        // 109440 bytes

__global__ __launch_bounds__(128) void attn_kernel(
    const __half* __restrict__ qkv, __half* __restrict__ outp)
{
    extern __shared__ float sm[];
    float* qs = sm;
    float* ks = sm + AOFF_K;
    float* vs = sm + AOFF_V;
    const int t    = threadIdx.x;
    const int warp = t >> 5;
    const int lane = t & 31;
    const int win  = blockIdx.x;
    float* Pt   = sm + AOFF_P + warp*16*AP_STR;
    float* invs = sm + AOFF_I + warp*16;

    const __half* base = qkv + (size_t)win*49*384;
    for (int idx = t; idx < 49*48; idx += 128) {
        int row = idx / 48;
        int sub = idx - row*48;
        int kind = sub >> 4;
        int c8 = sub & 15;
        uint4 hv = *(const uint4*)(base + (size_t)row*384 + kind*128 + c8*8);
        const __half2* hp = (const __half2*)&hv;
        float* dst = (kind == 0 ? qs + row*AQ_STR :
                      kind == 1 ? ks + row*AK_STR : vs + row*AV_STR) + c8*8;
        float2 f0 = __half22float2(hp[0]);
        float2 f1 = __half22float2(hp[1]);
        float2 f2 = __half22float2(hp[2]);
        float2 f3 = __half22float2(hp[3]);
        float4 o0; o0.x = f0.x; o0.y = f0.y; o0.z = f1.x; o0.w = f1.y;
        float4 o1; o1.x = f2.x; o1.y = f2.y; o1.z = f3.x; o1.w = f3.y;
        *(float4*)dst = o0;
        *(float4*)(dst + 4) = o1;
    }
    for (int idx = t; idx < 7*AV_STR; idx += 128) {
        int r = idx / AV_STR, c = idx - r*AV_STR;
        vs[(49+r)*AV_STR + c] = 0.f;
        if (c < AK_STR) ks[(49+r)*AK_STR + c] = 0.f;
    }
    __syncthreads();

    const int h   = warp;
    const int qr  = lane >> 2;
    const int qc  = lane & 3;
    const int h32 = h * 32;
    const float* comb = g_bias + (size_t)((win & 63)*4 + h)*2401;
    __half* obase = outp + (size_t)win*49*128 + h32;

    for (int mt = 0; mt < 4; mt++) {
        const int r0 = mt*16 + qr;
        const int r1 = r0 + 8;
        float s[7][4];
        #pragma unroll
        for (int jn = 0; jn < 7; jn++)
            #pragma unroll
            for (int c = 0; c < 4; c++) s[jn][c] = 0.f;
        #pragma unroll
        for (int kb = 0; kb < 32; kb += 8) {
            uint32_t a[4];
            a[0] = __float_as_uint(qs[(size_t)r0*AQ_STR + h32 + kb + qc    ]);
            a[1] = __float_as_uint(qs[(size_t)r1*AQ_STR + h32 + kb + qc    ]);
            a[2] = __float_as_uint(qs[(size_t)r0*AQ_STR + h32 + kb + qc + 4]);
            a[3] = __float_as_uint(qs[(size_t)r1*AQ_STR + h32 + kb + qc + 4]);
            #pragma unroll
            for (int jn = 0; jn < 7; jn++) {
                int n0 = jn*8 + qr;
                uint32_t b0 = __float_as_uint(ks[(size_t)n0*AK_STR + h32 + kb + qc    ]);
                uint32_t b1 = __float_as_uint(ks[(size_t)n0*AK_STR + h32 + kb + qc + 4]);
                mma_tf32(s[jn], a, b0, b1);
            }
        }
        const bool v0 = (r0 < 49), v1 = (r1 < 49);
        float mx0 = -1e30f, mx1 = -1e30f;
        #pragma unroll
        for (int jn = 0; jn < 7; jn++) {
            #pragma unroll
            for (int e = 0; e < 2; e++) {
                int col = jn*8 + qc*2 + e;
                if (col < 49) {
                    if (v0) s[jn][e]     += comb[r0*49 + col];
                    if (v1) s[jn][2 + e] += comb[r1*49 + col];
                } else {
                    s[jn][e] = -1e30f; s[jn][2 + e] = -1e30f;
                }
                mx0 = fmaxf(mx0, s[jn][e]);
                mx1 = fmaxf(mx1, s[jn][2 + e]);
            }
        }
        #pragma unroll
        for (int o = 1; o <= 2; o <<= 1) {
            mx0 = fmaxf(mx0, __shfl_xor_sync(0xffffffffu, mx0, o));
            mx1 = fmaxf(mx1, __shfl_xor_sync(0xffffffffu, mx1, o));
        }
        float sum0 = 0.f, sum1 = 0.f;
        #pragma unroll
        for (int jn = 0; jn < 7; jn++) {
            #pragma unroll
            for (int e = 0; e < 2; e++) {
                int col = jn*8 + qc*2 + e;
                float e0 = __expf(s[jn][e]     - mx0);
                float e1 = __expf(s[jn][2 + e] - mx1);
                sum0 += e0; sum1 += e1;
                Pt[qr*AP_STR       + col] = tf32r(e0);
                Pt[(qr + 8)*AP_STR + col] = tf32r(e1);
            }
        }
        #pragma unroll
        for (int o = 1; o <= 2; o <<= 1) {
            sum0 += __shfl_xor_sync(0xffffffffu, sum0, o);
            sum1 += __shfl_xor_sync(0xffffffffu, sum1, o);
        }
        if (qc == 0) {
            invs[qr]     = 1.0f / sum0;
            invs[qr + 8] = 1.0f / sum1;
        }
        __syncwarp();
        float o[4][4];
        #pragma unroll
        for (int jn = 0; jn < 4; jn++)
            #pragma unroll
            for (int c = 0; c < 4; c++) o[jn][c] = 0.f;
        #pragma unroll
        for (int ks2 = 0; ks2 < 7; ks2++) {
            const int kb = ks2*8;
            uint32_t a[4];
            a[0] = __float_as_uint(Pt[qr*AP_STR       + kb + qc    ]);
            a[1] = __float_as_uint(Pt[(qr + 8)*AP_STR + kb + qc    ]);
            a[2] = __float_as_uint(Pt[qr*AP_STR       + kb + qc + 4]);
            a[3] = __float_as_uint(Pt[(qr + 8)*AP_STR + kb + qc + 4]);
            #pragma unroll
            for (int jn = 0; jn < 4; jn++) {
                int n0 = jn*8 + qr;
                uint32_t b0 = __float_as_uint(vs[(size_t)(kb + qc    )*AV_STR + h32 + n0]);
                uint32_t b1 = __float_as_uint(vs[(size_t)(kb + qc + 4)*AV_STR + h32 + n0]);
                mma_tf32(o[jn], a, b0, b1);
            }
        }
        float i0 = invs[qr], i1 = invs[qr + 8];
        #pragma unroll
        for (int jn = 0; jn < 4; jn++) {
            int col = jn*8 + qc*2;
            if (v0) {
                __half2 f = __floats2half2_rn(o[jn][0]*i0, o[jn][1]*i0);
                *(__half2*)(obase + (size_t)r0*128 + col) = f;
            }
            if (v1) {
                __half2 f = __floats2half2_rn(o[jn][2]*i1, o[jn][3]*i1);
                *(__half2*)(obase + (size_t)r1*128 + col) = f;
            }
        }
        __syncwarp();
    }
}

// ---------------- FP16 tensor-core GEMM, 3-stage cp.async ring ------------
// C[M,Nd] = A[M,K] @ W[Nd,K]^T + epilogue. A and W are fp16.
// Block tile 128x128, BK=32, 8 warps (4m x 2n), warp tile 32x64, m16n8k16.
// 3 stages in smem; two stages always in flight (wait_group 2).
// Epilogue stores vectorized: half2 (EPI 1/3) / float2 (EPI 0/2/4).
#define TG_STG_BYTES (256*80)       // one stage: (128 A + 128 B rows) * 80B
#define TG_NSTG 3
#define TG_SMEM (TG_STG_BYTES*TG_NSTG)   // 61440 bytes

template<int EPI>
__global__ __launch_bounds__(256, 2) void tgemm_kernel(
    const __half* __restrict__ A, const __half* __restrict__ W,
    const float* __restrict__ bias, void* __restrict__ Cv,
    const float* __restrict__ aux, int M, int Nd, int K)
{
    extern __shared__ __align__(16) char dsm[];
    const int t    = threadIdx.x;
    const int warp = t >> 5;
    const int lane = t & 31;
    const int qr   = lane >> 2;
    const int qc   = lane & 3;
    const int wm   = warp & 3;    // m warp 0..3
    const int wn   = warp >> 2;   // n warp 0..1
    const int bm   = blockIdx.y * 128;
    const int bn   = blockIdx.x * 128;
    const int rowX = t >> 2;      // 0..63
    const int cX   = t & 3;       // 8-half chunk within 32-half row slice

    const __half* aG = A + (size_t)(bm + rowX)*K + cX*8;
    const __half* wG = W + (size_t)(bn + rowX)*K + cX*8;
    const size_t r64 = (size_t)64 * K;

    uint32_t s0 = (uint32_t)__cvta_generic_to_shared(dsm);
    const uint32_t sA = s0 + rowX*80 + cX*16;
    const uint32_t sB = sA + 128*80;

    float acc[2][8][4] = {};
    const int iters = K >> 5;   // >= 4 always (K = 128 or 512)

    // stage-load macro: k-iter kk into ring slot st
    #define TG_STAGE_LOAD(st, kk) do {                        \
        uint32_t off_ = (uint32_t)(st)*TG_STG_BYTES;          \
        const __half* ag_ = aG + (size_t)(kk)*32;             \
        const __half* wg_ = wG + (size_t)(kk)*32;             \
        cp_async16(sA + off_,         ag_);                   \
        cp_async16(sA + off_ + 64*80, ag_ + r64);             \
        cp_async16(sB + off_,         wg_);                   \
        cp_async16(sB + off_ + 64*80, wg_ + r64);             \
        cp_commit();                                          \
    } while (0)

    // prologue: stages 0 and 1
    TG_STAGE_LOAD(0, 0);
    TG_STAGE_LOAD(1, 1);

    int slot = 0;
    for (int it = 0; it < iters; it++) {
        if (it + 2 < iters) {
            int ps = slot + 2; if (ps >= TG_NSTG) ps -= TG_NSTG;
            TG_STAGE_LOAD(ps, it + 2);
            cp_wait2();
        } else if (it + 1 < iters) {
            cp_wait1();
        } else {
            cp_wait0();
        }
        __syncthreads();

        const uint32_t* As2 = (const uint32_t*)(dsm + slot*TG_STG_BYTES);  // half2 view, row stride 20
        const uint32_t* Bs2 = As2 + 128*20;
        #pragma unroll
        for (int ks = 0; ks < 2; ks++) {
            const int kb = ks * 8;   // half2 units (k = 16 per step)
            uint32_t af[2][4];
            #pragma unroll
            for (int i = 0; i < 2; i++) {
                int m0 = wm*32 + i*16 + qr;
                af[i][0] = As2[ m0     *20 + kb + qc    ];
                af[i][1] = As2[(m0 + 8)*20 + kb + qc    ];
                af[i][2] = As2[ m0     *20 + kb + qc + 4];
                af[i][3] = As2[(m0 + 8)*20 + kb + qc + 4];
            }
            #pragma unroll
            for (int j = 0; j < 8; j++) {
                int n0 = wn*64 + j*8 + qr;
                uint32_t b0 = Bs2[n0*20 + kb + qc    ];
                uint32_t b1 = Bs2[n0*20 + kb + qc + 4];
                mma_f16(acc[0][j], af[0], b0, b1);
                mma_f16(acc[1][j], af[1], b0, b1);
            }
        }
        __syncthreads();
        if (++slot == TG_NSTG) slot = 0;
    }
    #undef TG_STAGE_LOAD

    // ---- epilogue (vectorized pair stores) ----
    float*  Cf = (float*)Cv;
    __half* Ch = (__half*)Cv;
    #pragma unroll
    for (int i = 0; i < 2; i++) {
        #pragma unroll
        for (int half_ = 0; half_ < 2; half_++) {
            const int m = bm + wm*32 + i*16 + qr + half_*8;
            size_t obase;
            if (EPI == 2) {
                int win = m / 49, nn = m - win*49;
                int bb = win >> 6, w = win & 63;
                int n7 = nn / 7;
                int pi = (w >> 3)*7 + n7;
                int pj = (w & 7)*7 + (nn - n7*7);
                int ii = pi + 3; if (ii >= 56) ii -= 56;
                int jj = pj + 3; if (jj >= 56) jj -= 56;
                obase = (((size_t)bb*56 + ii)*56 + jj)*128;
            } else {
                obase = (size_t)m * Nd;
            }
            #pragma unroll
            for (int j = 0; j < 8; j++) {
                const int n = bn + wn*64 + j*8 + qc*2;
                float v0 = acc[i][j][half_*2];
                float v1 = acc[i][j][half_*2 + 1];
                if (EPI == 0) {
                    float2 f; f.x = v0; f.y = v1;
                    *(float2*)(Cf + obase + n) = f;
                } else if (EPI == 1) {
                    v0 += bias[n]; v1 += bias[n + 1];
                    if (n < 128) { v0 *= 0.17677669529663687f; v1 *= 0.17677669529663687f; }
                    *(__half2*)(Ch + obase + n) = __floats2half2_rn(v0, v1);
                } else if (EPI == 2) {
                    v0 += bias[n]; v1 += bias[n + 1];
                    float2 a2 = *(const float2*)(aux + obase + n);
                    float2 f; f.x = v0 + a2.x; f.y = v1 + a2.y;
                    *(float2*)(Cf + obase + n) = f;
                } else if (EPI == 3) {
                    v0 += bias[n]; v1 += bias[n + 1];
                    v0 = 0.5f * v0 * (1.0f + erff(v0 * 0.70710678118654752f));
                    v1 = 0.5f * v1 * (1.0f + erff(v1 * 0.70710678118654752f));
                    *(__half2*)(Ch + obase + n) = __floats2half2_rn(v0, v1);
                } else { // EPI == 4
                    v0 += bias[n]; v1 += bias[n + 1];
                    float2 a2 = *(const float2*)(aux + obase + n);
                    float2 f; f.x = v0 + a2.x; f.y = v1 + a2.y;
                    *(float2*)(Cf + obase + n) = f;
                }
            }
        }
    }
}

// ---------------- launcher ----------------
extern "C" void kernel_launch(void* const* d_in, const int* in_sizes, int n_in,
                              void* d_out, int out_size)
{
    const float* x       = (const float*)d_in[0];
    const float* n1w     = (const float*)d_in[1];
    const float* n1b     = (const float*)d_in[2];
    const float* qkv_w   = (const float*)d_in[3];
    const float* qkv_b   = (const float*)d_in[4];
    const float* proj_w  = (const float*)d_in[5];
    const float* proj_b  = (const float*)d_in[6];
    const float* rpb     = (const float*)d_in[7];
    const float* n2w     = (const float*)d_in[8];
    const float* n2b     = (const float*)d_in[9];
    const float* fc1_w   = (const float*)d_in[10];
    const float* fc1_b   = (const float*)d_in[11];
    const float* fc2_w   = (const float*)d_in[12];
    const float* fc2_b   = (const float*)d_in[13];
    const float* mnw     = (const float*)d_in[14];
    const float* mnb     = (const float*)d_in[15];
    const float* merge_w = (const float*)d_in[16];
    const int*   rel_idx = (const int*)d_in[17];
    const float* amask   = (const float*)d_in[18];
    float* out = (float*)d_out;

    __half *hw, *qkv, *o, *fc1, *wt;
    float *xres;
    cudaGetSymbolAddress((void**)&hw,   g_hw);
    cudaGetSymbolAddress((void**)&qkv,  g_qkv);
    cudaGetSymbolAddress((void**)&o,    g_o);
    cudaGetSymbolAddress((void**)&xres, g_xres);
    cudaGetSymbolAddress((void**)&fc1,  g_fc1);
    cudaGetSymbolAddress((void**)&wt,   g_wt);

    cudaFuncSetAttribute(tgemm_kernel<0>, cudaFuncAttributeMaxDynamicSharedMemorySize, TG_SMEM);
    cudaFuncSetAttribute(tgemm_kernel<1>, cudaFuncAttributeMaxDynamicSharedMemorySize, TG_SMEM);
    cudaFuncSetAttribute(tgemm_kernel<2>, cudaFuncAttributeMaxDynamicSharedMemorySize, TG_SMEM);
    cudaFuncSetAttribute(tgemm_kernel<3>, cudaFuncAttributeMaxDynamicSharedMemorySize, TG_SMEM);
    cudaFuncSetAttribute(tgemm_kernel<4>, cudaFuncAttributeMaxDynamicSharedMemorySize, TG_SMEM);
    cudaFuncSetAttribute(attn_kernel, cudaFuncAttributeMaxDynamicSharedMemorySize, ATT_SMEM);

    // 0. pre-convert weights to fp16; build combined attention bias table
    round_w_kernel<<<WTOT/256, 256>>>(qkv_w, proj_w, fc1_w, fc2_w, merge_w);
    bias_prep_kernel<<<dim3(64, 4), 256>>>(rpb, rel_idx, amask);
    // 1. LN1 + roll + window partition (fp16 out)
    ln1_win_kernel<<<PIX/8, 256>>>(x, n1w, n1b);
    // 2. qkv GEMM (scale folded into q; fp16 out)
    tgemm_kernel<1><<<dim3(3, M1_/128), 256, TG_SMEM>>>(hw, wt + WOFF_QKV, qkv_b, qkv, nullptr, M1_, 384, 128);
    // 3. windowed attention (tensor cores; fp16 out)
    attn_kernel<<<4096, 128, ATT_SMEM>>>(qkv, o);
    // 4. proj GEMM + window-reverse + roll-back + residual -> xres (fp32, pixel layout)
    tgemm_kernel<2><<<dim3(1, M1_/128), 256, TG_SMEM>>>(o, wt + WOFF_PROJ, proj_b, xres, x, M1_, 128, 128);
    // 5. LN2: xres -> g_hw (fp16)
    ln2_kernel<<<PIX/8, 256>>>(n2w, n2b);
    // 6. fc1 GEMM + GELU (fp16 out)
    tgemm_kernel<3><<<dim3(4, M1_/128), 256, TG_SMEM>>>(hw, wt + WOFF_FC1, fc1_b, fc1, nullptr, M1_, 512, 128);
    // 7. fc2 GEMM + residual (fp32, in place on xres)
    tgemm_kernel<4><<<dim3(1, M1_/128), 256, TG_SMEM>>>(fc1, wt + WOFF_FC2, fc2_b, xres, xres, M1_, 128, 512);
    // 8. patch-merge gather + LN(512): xres -> g_o (fp16, reuse as xm)
    merge_ln_kernel<<<M2_/8, 256>>>(mnw, mnb);
    // 9. merge GEMM -> output (fp32)
    tgemm_kernel<0><<<dim3(2, M2_/128), 256, TG_SMEM>>>(o, wt + WOFF_MRG, nullptr, out, nullptr, M2_, 256, 512);
}